// round 14
// baseline (speedup 1.0000x reference)
#include <cuda_runtime.h>
#include <cuda_fp16.h>
#include <math.h>

#define N_NODES 50000
#define N_ENV   1000000
#define N_EDGES 200000
#define NDD     512              // D * N_AXIS = 64*8
#define NODE_OUT_ELEMS (N_NODES * NDD)

// Scratch
__device__ float g_summ[N_NODES * 192];   // [node][3][64]; zeroed, atomically accumulated
__device__ int   g_counts[N_NODES];
__device__ int   g_start[N_NODES];
__device__ int   g_cursor[N_NODES];
__device__ float4 s_a[N_ENV];             // sorted: (vx,vy,vz,snorm)
__device__ float4 s_b[N_ENV];             // sorted: attr of endpoint 0
__device__ float4 s_c[N_ENV];             // sorted: attr of endpoint 1
__device__ int    s_node[N_ENV];          // sorted: target node

typedef unsigned long long u64;
typedef unsigned int u32;

__device__ __forceinline__ u64 pack2(float lo, float hi) {
    u64 r; asm("mov.b64 %0, {%1,%2};" : "=l"(r) : "f"(lo), "f"(hi)); return r;
}
__device__ __forceinline__ void unpack2(u64 v, float& lo, float& hi) {
    asm("mov.b64 {%0,%1}, %2;" : "=f"(lo), "=f"(hi) : "l"(v));
}
__device__ __forceinline__ u64 fma2(u64 a, u64 b, u64 c) {
    u64 d; asm("fma.rn.f32x2 %0, %1, %2, %3;" : "=l"(d) : "l"(a), "l"(b), "l"(c)); return d;
}
__device__ __forceinline__ float tanh_fast(float x) {
    float y; asm("tanh.approx.f32 %0, %1;" : "=f"(y) : "f"(x)); return y;
}
__device__ __forceinline__ u32 packh2(float a, float b) {
    __half2 h = __floats2half2_rn(a, b);
    return *reinterpret_cast<u32*>(&h);
}
__device__ __forceinline__ void red_add_v4(float* p, float a, float b, float c, float d) {
    asm volatile("red.global.add.v4.f32 [%0], {%1,%2,%3,%4};"
                 :: "l"(p), "f"(a), "f"(b), "f"(c), "f"(d) : "memory");
}
__device__ __forceinline__ void st_cs_v4(float* p, float4 v) {
    asm volatile("st.global.cs.v4.f32 [%0], {%1,%2,%3,%4};"
                 :: "l"(p), "f"(v.x), "f"(v.y), "f"(v.z), "f"(v.w) : "memory");
}
__device__ __forceinline__ void mma_f16(float* d, u32 a0, u32 a1, u32 b0) {
    asm volatile(
        "mma.sync.aligned.m16n8k8.row.col.f32.f16.f16.f32 "
        "{%0,%1,%2,%3},{%4,%5},{%6},{%0,%1,%2,%3};"
        : "+f"(d[0]), "+f"(d[1]), "+f"(d[2]), "+f"(d[3])
        : "r"(a0), "r"(a1), "r"(b0));
}

// ============ prologue ============

__global__ void zero_kernel() {
    int i = blockIdx.x * blockDim.x + threadIdx.x;
    int stride = gridDim.x * blockDim.x;
    float4* p = (float4*)g_summ;
    const float4 z = make_float4(0.f, 0.f, 0.f, 0.f);
    for (int k = i; k < N_NODES * 48; k += stride) p[k] = z;
    for (int k = i; k < N_NODES; k += stride) g_counts[k] = 0;
}

__global__ void hist_kernel(const int* __restrict__ env_index) {
    int e = blockIdx.x * blockDim.x + threadIdx.x;
    if (e < N_ENV) atomicAdd(&g_counts[env_index[N_ENV + e]], 1);
}

__global__ void scan_kernel() {
    const int T = 1024, CH = (N_NODES + T - 1) / T;
    __shared__ int ssum[T];
    int t = threadIdx.x;
    int lo = t * CH, hi = min(lo + CH, N_NODES);
    int local = 0;
    for (int i = lo; i < hi; i++) local += g_counts[i];
    ssum[t] = local;
    __syncthreads();
    int acc = local;
    for (int off = 1; off < T; off *= 2) {
        int v = (t >= off) ? ssum[t - off] : 0;
        __syncthreads();
        ssum[t] += v;
        __syncthreads();
    }
    int run = ssum[t] - acc;
    for (int i = lo; i < hi; i++) {
        g_start[i] = run;
        g_cursor[i] = run;
        run += g_counts[i];
    }
}

// Materialize sorted inputs (coalesced reads, scattered 52B writes) + snorm.
__global__ void permute_kernel(const int* __restrict__ env_index,
                               const float* __restrict__ env_vectors,
                               const float* __restrict__ atom_attr) {
    int e = blockIdx.x * blockDim.x + threadIdx.x;
    if (e >= N_ENV) return;
    int node = env_index[N_ENV + e];
    int pos = atomicAdd(&g_cursor[node], 1);

    float vx = env_vectors[3 * e + 0];
    float vy = env_vectors[3 * e + 1];
    float vz = env_vectors[3 * e + 2];
    float r = sqrtf(vx * vx + vy * vy + vz * vz);
    float inv_r = 1.0f / r;
    float snorm;
    if (r < 3.0f) snorm = inv_r;
    else if (r < 6.0f) {
        float u = (r - 6.0f) * (-1.0f / 3.0f);
        snorm = inv_r * (u * u * u * (10.0f + u * (-15.0f + 6.0f * u)) + 1.0f);
    } else snorm = 0.0f;

    int i0 = env_index[e];
    s_a[pos] = make_float4(vx, vy, vz, snorm);
    s_b[pos] = *(const float4*)&atom_attr[4 * i0];
    s_c[pos] = *(const float4*)&atom_attr[4 * node];
    s_node[pos] = node;
}

// ============ env MLP (sorted, f16 mma, segmented-atomic epilogue) ============

#define OFF_W1  0        // 288 f32
#define OFF_B1  288      // 32 f32
#define OFF_B2  320      // 64 f32
#define OFF_B3  384      // 64 f32
#define OFF_W2H 448      // 64 n x 20 words f16x2
#define OFF_W3H 1728     // 64 n x 36 words f16x2
#define OFF_H   4032     // per warp: H1 32x20 + H2 16x36
#define WARP_H_WORDS (32 * 20 + 16 * 36)   // 1216
#define SMEM_WORDS (OFF_H + 8 * WARP_H_WORDS)  // 13760 words = 55040 B
#define N_WARPS_TOTAL (N_ENV / 32)

__global__ void __launch_bounds__(256, 3) env_kernel(
    const float* __restrict__ W1, const float* __restrict__ b1,
    const float* __restrict__ W2, const float* __restrict__ b2,
    const float* __restrict__ W3, const float* __restrict__ b3)
{
    extern __shared__ __align__(16) u32 smu[];
    float* smf = (float*)smu;
    int tid = threadIdx.x;

    for (int i = tid; i < 288; i += 256) smf[OFF_W1 + i] = W1[i];
    for (int i = tid; i < 32;  i += 256) smf[OFF_B1 + i] = b1[i];
    for (int i = tid; i < 64;  i += 256) smf[OFF_B2 + i] = b2[i];
    for (int i = tid; i < 64;  i += 256) smf[OFF_B3 + i] = b3[i];
    for (int i = tid; i < 64 * 16; i += 256) {
        int n = i >> 4, kw = i & 15;
        smu[OFF_W2H + n * 20 + kw] = packh2(W2[(2 * kw) * 64 + n], W2[(2 * kw + 1) * 64 + n]);
    }
    for (int i = tid; i < 64 * 32; i += 256) {
        int n = i >> 5, kw = i & 31;
        smu[OFF_W3H + n * 36 + kw] = packh2(W3[(2 * kw) * 64 + n], W3[(2 * kw + 1) * 64 + n]);
    }
    __syncthreads();

    int wid  = tid >> 5;
    int lane = tid & 31;
    int warpg = blockIdx.x * 8 + wid;
    if (warpg >= N_WARPS_TOTAL) return;
    int p_base = warpg * 32;

    u32* H1 = &smu[OFF_H + wid * WARP_H_WORDS];
    u32* H2 = H1 + 32 * 20;
    const float* sW1 = &smf[OFF_W1];
    const float* sb1 = &smf[OFF_B1];
    const float* sb2 = &smf[OFF_B2];
    const float* sb3 = &smf[OFF_B3];

    // ---- layer 1 (exact fp32), lane = sorted position (coalesced) ----
    {
        float4 av = s_a[p_base + lane];
        float4 b4 = s_b[p_base + lane];
        float4 c4 = s_c[p_base + lane];

        u64 inp[9];
        inp[0] = pack2(av.w, av.w);
        inp[1] = pack2(b4.x, b4.x); inp[2] = pack2(b4.y, b4.y);
        inp[3] = pack2(b4.z, b4.z); inp[4] = pack2(b4.w, b4.w);
        inp[5] = pack2(c4.x, c4.x); inp[6] = pack2(c4.y, c4.y);
        inp[7] = pack2(c4.z, c4.z); inp[8] = pack2(c4.w, c4.w);

        float h1[32];
#pragma unroll
        for (int j = 0; j < 32; j += 4) {
            ulonglong2 b = *(const ulonglong2*)&sb1[j];
            u64 s0 = b.x, s1 = b.y;
#pragma unroll
            for (int i = 0; i < 9; i++) {
                ulonglong2 w = *(const ulonglong2*)&sW1[i * 32 + j];
                s0 = fma2(inp[i], w.x, s0);
                s1 = fma2(inp[i], w.y, s1);
            }
            float x0, x1, x2, x3;
            unpack2(s0, x0, x1); unpack2(s1, x2, x3);
            h1[j + 0] = tanh_fast(x0);
            h1[j + 1] = tanh_fast(x1);
            h1[j + 2] = tanh_fast(x2);
            h1[j + 3] = tanh_fast(x3);
        }
#pragma unroll
        for (int k = 0; k < 16; k++)
            H1[lane * 20 + k] = packh2(h1[2 * k], h1[2 * k + 1]);
    }
    __syncwarp();

    int gid = lane >> 2;
    int tg  = lane & 3;
    const u32* W2u = &smu[OFF_W2H];
    const u32* W3u = &smu[OFF_W3H];

    for (int m = 0; m < 2; m++) {
        int r1A = (m * 16 + gid) * 20;
        int r1B = (m * 16 + gid + 8) * 20;

        // ---- layer 2 ----
        float h2r[8][4];
#pragma unroll
        for (int nt = 0; nt < 8; nt++) {
            float bb0 = sb2[nt * 8 + tg * 2], bb1 = sb2[nt * 8 + tg * 2 + 1];
            h2r[nt][0] = bb0; h2r[nt][1] = bb1; h2r[nt][2] = bb0; h2r[nt][3] = bb1;
        }
#pragma unroll
        for (int kt = 0; kt < 4; kt++) {
            u32 a0 = H1[r1A + 4 * kt + tg];
            u32 a1 = H1[r1B + 4 * kt + tg];
#pragma unroll
            for (int nt = 0; nt < 8; nt++) {
                u32 b = W2u[(nt * 8 + gid) * 20 + 4 * kt + tg];
                mma_f16(h2r[nt], a0, a1, b);
            }
        }
#pragma unroll
        for (int nt = 0; nt < 8; nt++) {
            h2r[nt][0] = tanh_fast(h2r[nt][0]);
            h2r[nt][1] = tanh_fast(h2r[nt][1]);
            h2r[nt][2] = tanh_fast(h2r[nt][2]);
            h2r[nt][3] = tanh_fast(h2r[nt][3]);
        }
        __syncwarp();
#pragma unroll
        for (int nt = 0; nt < 8; nt++) {
            H2[gid * 36 + nt * 4 + tg]       = packh2(h2r[nt][0], h2r[nt][1]);
            H2[(gid + 8) * 36 + nt * 4 + tg] = packh2(h2r[nt][2], h2r[nt][3]);
        }
        __syncwarp();

        // ---- per-m epilogue context: lane's row = sorted position ----
        int odd = tg & 1;
        int row = p_base + m * 16 + gid + 8 * odd;
        float4 av = s_a[row];
        float vx = av.x, vy = av.y, vz = av.z;
        int node_own = s_node[row];
        float* base = &g_summ[(long long)node_own * 192];
        int col4 = (tg & 2) * 2;

        // segmented-reduction conditions across gid (stride-4 lanes, same tg class)
        int n4  = __shfl_down_sync(0xffffffff, node_own, 4);
        int n8  = __shfl_down_sync(0xffffffff, node_own, 8);
        int n16 = __shfl_down_sync(0xffffffff, node_own, 16);
        bool c4  = (lane + 4  < 32) && (n4  == node_own);
        bool c8  = (lane + 8  < 32) && (n8  == node_own);
        bool c16 = (lane + 16 < 32) && (n16 == node_own);
        int nup = __shfl_up_sync(0xffffffff, node_own, 4);
        bool is_head = (gid == 0) || (nup != node_own);

        // ---- layer 3 (2 passes of 4 nt) + segmented scatter ----
#pragma unroll
        for (int np = 0; np < 2; np++) {
            float d3[4][4];
#pragma unroll
            for (int j = 0; j < 4; j++) {
                int nt = np * 4 + j;
                float bb0 = sb3[nt * 8 + tg * 2], bb1 = sb3[nt * 8 + tg * 2 + 1];
                d3[j][0] = bb0; d3[j][1] = bb1; d3[j][2] = bb0; d3[j][3] = bb1;
            }
#pragma unroll
            for (int kt = 0; kt < 8; kt++) {
                u32 a0 = H2[gid * 36 + 4 * kt + tg];
                u32 a1 = H2[(gid + 8) * 36 + 4 * kt + tg];
#pragma unroll
                for (int j = 0; j < 4; j++) {
                    u32 b = W3u[((np * 4 + j) * 8 + gid) * 36 + 4 * kt + tg];
                    mma_f16(d3[j], a0, a1, b);
                }
            }
#pragma unroll
            for (int j = 0; j < 4; j++) {
                int nt = np * 4 + j;
                float oA0 = tanh_fast(d3[j][0]) + h2r[nt][0];
                float oA1 = tanh_fast(d3[j][1]) + h2r[nt][1];
                float oB0 = tanh_fast(d3[j][2]) + h2r[nt][2];
                float oB1 = tanh_fast(d3[j][3]) + h2r[nt][3];
                float pA0 = __shfl_xor_sync(0xffffffff, oA0, 1);
                float pA1 = __shfl_xor_sync(0xffffffff, oA1, 1);
                float pB0 = __shfl_xor_sync(0xffffffff, oB0, 1);
                float pB1 = __shfl_xor_sync(0xffffffff, oB1, 1);
                float q0 = odd ? pB0 : oA0;
                float q1 = odd ? pB1 : oA1;
                float q2 = odd ? oB0 : pA0;
                float q3 = odd ? oB1 : pA1;

                // 12 products, segmented suffix-sum over gid, heads scatter
                float p_[12];
                p_[0] = q0 * vx; p_[1] = q1 * vx; p_[2]  = q2 * vx; p_[3]  = q3 * vx;
                p_[4] = q0 * vy; p_[5] = q1 * vy; p_[6]  = q2 * vy; p_[7]  = q3 * vy;
                p_[8] = q0 * vz; p_[9] = q1 * vz; p_[10] = q2 * vz; p_[11] = q3 * vz;
#pragma unroll
                for (int v = 0; v < 12; v++) {
                    float t4 = __shfl_down_sync(0xffffffff, p_[v], 4);
                    p_[v] += c4 ? t4 : 0.f;
                }
#pragma unroll
                for (int v = 0; v < 12; v++) {
                    float t8 = __shfl_down_sync(0xffffffff, p_[v], 8);
                    p_[v] += c8 ? t8 : 0.f;
                }
#pragma unroll
                for (int v = 0; v < 12; v++) {
                    float t16 = __shfl_down_sync(0xffffffff, p_[v], 16);
                    p_[v] += c16 ? t16 : 0.f;
                }
                if (is_head) {
                    int off = nt * 8 + col4;
                    red_add_v4(base +   0 + off, p_[0], p_[1], p_[2],  p_[3]);
                    red_add_v4(base +  64 + off, p_[4], p_[5], p_[6],  p_[7]);
                    red_add_v4(base + 128 + off, p_[8], p_[9], p_[10], p_[11]);
                }
            }
        }
    }
}

// ============ node kernel (counts from histogram; aggr in place) ============
__global__ void __launch_bounds__(256) node_kernel(float* __restrict__ out)
{
    int t = threadIdx.x;
    int local = t >> 6;
    int d = t & 63;
    int n = blockIdx.x * 4 + local;

    __shared__ float sA[4][3][8];

    float cnt = (float)g_counts[n];
    float inv = 1.0f / fmaxf(cnt, 1.0f);
    float* base = &g_summ[(long long)n * 192];
    float c0 = base[  0 + d] * inv;
    float c1 = base[ 64 + d] * inv;
    float c2 = base[128 + d] * inv;

    if (d < 8) {
        sA[local][0][d] = c0;
        sA[local][1][d] = c1;
        sA[local][2][d] = c2;
    }
    base[  0 + d] = c0;
    base[ 64 + d] = c1;
    base[128 + d] = c2;
    __syncthreads();

    float res[8];
#pragma unroll
    for (int a = 0; a < 8; a++)
        res[a] = c0 * sA[local][0][a] + c1 * sA[local][1][a] + c2 * sA[local][2][a];

    float4* op = (float4*)&out[(long long)n * NDD + d * 8];
    op[0] = make_float4(res[0], res[1], res[2], res[3]);
    op[1] = make_float4(res[4], res[5], res[6], res[7]);
}

// ============ edge kernel (recompute from aggr) ============
__global__ void __launch_bounds__(256) edge_kernel(
    const int* __restrict__ edge_index,
    float* __restrict__ out)
{
    int t = threadIdx.x;
    int g = t >> 6;
    int d = t & 63;
    int k = blockIdx.x * 4 + g;

    __shared__ float sA[4][2][3][8];

    int i = edge_index[k];
    int j = edge_index[N_EDGES + k];
    const float* Ai = &g_summ[(long long)i * 192];
    const float* Aj = &g_summ[(long long)j * 192];
    float ai0 = Ai[d], ai1 = Ai[64 + d], ai2 = Ai[128 + d];
    float aj0 = Aj[d], aj1 = Aj[64 + d], aj2 = Aj[128 + d];

    if (d < 8) {
        sA[g][0][0][d] = ai0; sA[g][0][1][d] = ai1; sA[g][0][2][d] = ai2;
        sA[g][1][0][d] = aj0; sA[g][1][1][d] = aj1; sA[g][1][2][d] = aj2;
    }
    __syncthreads();

    float res[8];
#pragma unroll
    for (int a = 0; a < 8; a++) {
        res[a] = ai0 * sA[g][0][0][a] + ai1 * sA[g][0][1][a] + ai2 * sA[g][0][2][a]
               + aj0 * sA[g][1][0][a] + aj1 * sA[g][1][1][a] + aj2 * sA[g][1][2][a];
    }

    float* op = &out[(long long)k * NDD + d * 8];
    st_cs_v4(op,     make_float4(res[0], res[1], res[2], res[3]));
    st_cs_v4(op + 4, make_float4(res[4], res[5], res[6], res[7]));
}

extern "C" void kernel_launch(void* const* d_in, const int* in_sizes, int n_in,
                              void* d_out, int out_size)
{
    const float* env_vectors = (const float*)d_in[0];
    const float* atom_attr   = (const float*)d_in[1];
    const int*   env_index   = (const int*)  d_in[2];
    const int*   edge_index  = (const int*)  d_in[3];
    const float* W1 = (const float*)d_in[4];
    const float* b1 = (const float*)d_in[5];
    const float* W2 = (const float*)d_in[6];
    const float* b2 = (const float*)d_in[7];
    const float* W3 = (const float*)d_in[8];
    const float* b3 = (const float*)d_in[9];

    float* out = (float*)d_out;
    float* node_out = out;                       // [50000, 512]
    float* edge_out = out + NODE_OUT_ELEMS;      // [200000, 512]

    size_t smem_bytes = SMEM_WORDS * sizeof(u32);   // 55040
    cudaFuncSetAttribute(env_kernel, cudaFuncAttributeMaxDynamicSharedMemorySize,
                         (int)smem_bytes);

    zero_kernel<<<2048, 256>>>();
    hist_kernel<<<(N_ENV + 255) / 256, 256>>>(env_index);
    scan_kernel<<<1, 1024>>>();
    permute_kernel<<<(N_ENV + 255) / 256, 256>>>(env_index, env_vectors, atom_attr);
    env_kernel<<<(N_WARPS_TOTAL + 7) / 8, 256, smem_bytes>>>(W1, b1, W2, b2, W3, b3);
    node_kernel<<<N_NODES / 4, 256>>>(node_out);
    edge_kernel<<<N_EDGES / 4, 256>>>(edge_index, edge_out);
}

// round 15
// speedup vs baseline: 1.4962x; 1.4962x over previous
#include <cuda_runtime.h>
#include <cuda_fp16.h>
#include <math.h>

#define N_NODES 50000
#define N_ENV   1000000
#define N_EDGES 200000
#define NDD     512              // D * N_AXIS = 64*8
#define NODE_OUT_ELEMS (N_NODES * NDD)

// Scratch
__device__ float g_summ[N_NODES * 192];        // aggr (mean), written directly by reduce
__device__ int   g_counts[N_NODES];
__device__ int   g_start[N_NODES];
__device__ int   g_cursor[N_NODES];
__device__ int   g_sorted[N_ENV];              // env ids sorted by target node
__device__ float4 g_v[N_ENV];                  // (vx,vy,vz,_) per env, original order
__device__ float g_o[(long long)N_ENV * 64];   // per-env MLP output row, ORIGINAL order

typedef unsigned long long u64;
typedef unsigned int u32;

__device__ __forceinline__ u64 pack2(float lo, float hi) {
    u64 r; asm("mov.b64 %0, {%1,%2};" : "=l"(r) : "f"(lo), "f"(hi)); return r;
}
__device__ __forceinline__ void unpack2(u64 v, float& lo, float& hi) {
    asm("mov.b64 {%0,%1}, %2;" : "=f"(lo), "=f"(hi) : "l"(v));
}
__device__ __forceinline__ u64 fma2(u64 a, u64 b, u64 c) {
    u64 d; asm("fma.rn.f32x2 %0, %1, %2, %3;" : "=l"(d) : "l"(a), "l"(b), "l"(c)); return d;
}
__device__ __forceinline__ float tanh_fast(float x) {
    float y; asm("tanh.approx.f32 %0, %1;" : "=f"(y) : "f"(x)); return y;
}
__device__ __forceinline__ u32 packh2(float a, float b) {
    __half2 h = __floats2half2_rn(a, b);
    return *reinterpret_cast<u32*>(&h);
}
__device__ __forceinline__ void st_cs_v2(float* p, float a, float b) {
    asm volatile("st.global.cs.v2.f32 [%0], {%1,%2};" :: "l"(p), "f"(a), "f"(b) : "memory");
}
__device__ __forceinline__ void st_cs_v4(float* p, float4 v) {
    asm volatile("st.global.cs.v4.f32 [%0], {%1,%2,%3,%4};"
                 :: "l"(p), "f"(v.x), "f"(v.y), "f"(v.z), "f"(v.w) : "memory");
}
// mma.m16n8k8 f16 (f32 accum).
// D/C frag: c0=(row=gid,col=2tg) c1=(gid,2tg+1) c2=(gid+8,2tg) c3=(gid+8,2tg+1)
__device__ __forceinline__ void mma_f16(float* d, u32 a0, u32 a1, u32 b0) {
    asm volatile(
        "mma.sync.aligned.m16n8k8.row.col.f32.f16.f16.f32 "
        "{%0,%1,%2,%3},{%4,%5},{%6},{%0,%1,%2,%3};"
        : "+f"(d[0]), "+f"(d[1]), "+f"(d[2]), "+f"(d[3])
        : "r"(a0), "r"(a1), "r"(b0));
}

// ============ prologue: counting sort of env ids by target node ============

__global__ void zero_counts_kernel() {
    int i = blockIdx.x * blockDim.x + threadIdx.x;
    if (i < N_NODES) g_counts[i] = 0;
}

__global__ void hist_kernel(const int* __restrict__ env_index) {
    int e = blockIdx.x * blockDim.x + threadIdx.x;
    if (e < N_ENV) atomicAdd(&g_counts[env_index[N_ENV + e]], 1);
}

__global__ void scan_kernel() {
    const int T = 1024, CH = (N_NODES + T - 1) / T;
    __shared__ int ssum[T];
    int t = threadIdx.x;
    int lo = t * CH, hi = min(lo + CH, N_NODES);
    int local = 0;
    for (int i = lo; i < hi; i++) local += g_counts[i];
    ssum[t] = local;
    __syncthreads();
    int acc = local;
    for (int off = 1; off < T; off *= 2) {
        int v = (t >= off) ? ssum[t - off] : 0;
        __syncthreads();
        ssum[t] += v;
        __syncthreads();
    }
    int run = ssum[t] - acc;
    for (int i = lo; i < hi; i++) {
        g_start[i] = run;
        g_cursor[i] = run;
        run += g_counts[i];
    }
}

__global__ void scatter_kernel(const int* __restrict__ env_index) {
    int e = blockIdx.x * blockDim.x + threadIdx.x;
    if (e < N_ENV) {
        int pos = atomicAdd(&g_cursor[env_index[N_ENV + e]], 1);
        g_sorted[pos] = e;
    }
}

// ============ env MLP (original order, fp16 mma, sequential o-row store) ============

#define OFF_W1  0        // 288 f32
#define OFF_B1  288      // 32 f32
#define OFF_B2  320      // 64 f32
#define OFF_B3  384      // 64 f32
#define OFF_W2H 448      // 64 n x 20 words f16x2
#define OFF_W3H 1728     // 64 n x 36 words f16x2
#define OFF_H   4032     // per warp: H1 32x20 + H2 16x36
#define WARP_H_WORDS (32 * 20 + 16 * 36)   // 1216
#define SMEM_WORDS (OFF_H + 8 * WARP_H_WORDS)  // 13760 words = 55040 B
#define N_WARPS_TOTAL (N_ENV / 32)

__global__ void __launch_bounds__(256, 3) env_kernel(
    const float* __restrict__ env_vectors,
    const float* __restrict__ atom_attr,
    const int*   __restrict__ env_index,
    const float* __restrict__ W1, const float* __restrict__ b1,
    const float* __restrict__ W2, const float* __restrict__ b2,
    const float* __restrict__ W3, const float* __restrict__ b3)
{
    extern __shared__ __align__(16) u32 smu[];
    float* smf = (float*)smu;
    int tid = threadIdx.x;

    for (int i = tid; i < 288; i += 256) smf[OFF_W1 + i] = W1[i];
    for (int i = tid; i < 32;  i += 256) smf[OFF_B1 + i] = b1[i];
    for (int i = tid; i < 64;  i += 256) smf[OFF_B2 + i] = b2[i];
    for (int i = tid; i < 64;  i += 256) smf[OFF_B3 + i] = b3[i];
    for (int i = tid; i < 64 * 16; i += 256) {
        int n = i >> 4, kw = i & 15;
        smu[OFF_W2H + n * 20 + kw] = packh2(W2[(2 * kw) * 64 + n], W2[(2 * kw + 1) * 64 + n]);
    }
    for (int i = tid; i < 64 * 32; i += 256) {
        int n = i >> 5, kw = i & 31;
        smu[OFF_W3H + n * 36 + kw] = packh2(W3[(2 * kw) * 64 + n], W3[(2 * kw + 1) * 64 + n]);
    }
    __syncthreads();

    int wid  = tid >> 5;
    int lane = tid & 31;
    int warpg = blockIdx.x * 8 + wid;
    if (warpg >= N_WARPS_TOTAL) return;
    int e_base = warpg * 32;

    u32* H1 = &smu[OFF_H + wid * WARP_H_WORDS];
    u32* H2 = H1 + 32 * 20;
    const float* sW1 = &smf[OFF_W1];
    const float* sb1 = &smf[OFF_B1];
    const float* sb2 = &smf[OFF_B2];
    const float* sb3 = &smf[OFF_B3];

    // ---- layer 1 (exact fp32), lane = env (sequential, coalesced) ----
    {
        int e = e_base + lane;
        float vx = env_vectors[3 * e + 0];
        float vy = env_vectors[3 * e + 1];
        float vz = env_vectors[3 * e + 2];
        float r = sqrtf(vx * vx + vy * vy + vz * vz);
        float inv_r = 1.0f / r;
        float snorm;
        if (r < 3.0f) snorm = inv_r;
        else if (r < 6.0f) {
            float u = (r - 6.0f) * (-1.0f / 3.0f);
            snorm = inv_r * (u * u * u * (10.0f + u * (-15.0f + 6.0f * u)) + 1.0f);
        } else snorm = 0.0f;

        // stage v for the reduce kernel (sequential 16B store)
        st_cs_v4((float*)&g_v[e], make_float4(vx, vy, vz, 0.f));

        int i0 = env_index[e];
        int i1 = env_index[N_ENV + e];
        float4 a0 = *(const float4*)&atom_attr[4 * i0];
        float4 a1 = *(const float4*)&atom_attr[4 * i1];

        u64 inp[9];
        inp[0] = pack2(snorm, snorm);
        inp[1] = pack2(a0.x, a0.x); inp[2] = pack2(a0.y, a0.y);
        inp[3] = pack2(a0.z, a0.z); inp[4] = pack2(a0.w, a0.w);
        inp[5] = pack2(a1.x, a1.x); inp[6] = pack2(a1.y, a1.y);
        inp[7] = pack2(a1.z, a1.z); inp[8] = pack2(a1.w, a1.w);

        float h1[32];
#pragma unroll
        for (int j = 0; j < 32; j += 4) {
            ulonglong2 b = *(const ulonglong2*)&sb1[j];
            u64 s0 = b.x, s1 = b.y;
#pragma unroll
            for (int i = 0; i < 9; i++) {
                ulonglong2 w = *(const ulonglong2*)&sW1[i * 32 + j];
                s0 = fma2(inp[i], w.x, s0);
                s1 = fma2(inp[i], w.y, s1);
            }
            float x0, x1, x2, x3;
            unpack2(s0, x0, x1); unpack2(s1, x2, x3);
            h1[j + 0] = tanh_fast(x0);
            h1[j + 1] = tanh_fast(x1);
            h1[j + 2] = tanh_fast(x2);
            h1[j + 3] = tanh_fast(x3);
        }
#pragma unroll
        for (int k = 0; k < 16; k++)
            H1[lane * 20 + k] = packh2(h1[2 * k], h1[2 * k + 1]);
    }
    __syncwarp();

    int gid = lane >> 2;
    int tg  = lane & 3;
    const u32* W2u = &smu[OFF_W2H];
    const u32* W3u = &smu[OFF_W3H];

    for (int m = 0; m < 2; m++) {
        int r1A = (m * 16 + gid) * 20;
        int r1B = (m * 16 + gid + 8) * 20;

        // ---- layer 2: K=32 ----
        float h2r[8][4];
#pragma unroll
        for (int nt = 0; nt < 8; nt++) {
            float bb0 = sb2[nt * 8 + tg * 2], bb1 = sb2[nt * 8 + tg * 2 + 1];
            h2r[nt][0] = bb0; h2r[nt][1] = bb1; h2r[nt][2] = bb0; h2r[nt][3] = bb1;
        }
#pragma unroll
        for (int kt = 0; kt < 4; kt++) {
            u32 a0 = H1[r1A + 4 * kt + tg];
            u32 a1 = H1[r1B + 4 * kt + tg];
#pragma unroll
            for (int nt = 0; nt < 8; nt++) {
                u32 b = W2u[(nt * 8 + gid) * 20 + 4 * kt + tg];
                mma_f16(h2r[nt], a0, a1, b);
            }
        }
#pragma unroll
        for (int nt = 0; nt < 8; nt++) {
            h2r[nt][0] = tanh_fast(h2r[nt][0]);
            h2r[nt][1] = tanh_fast(h2r[nt][1]);
            h2r[nt][2] = tanh_fast(h2r[nt][2]);
            h2r[nt][3] = tanh_fast(h2r[nt][3]);
        }
        __syncwarp();
#pragma unroll
        for (int nt = 0; nt < 8; nt++) {
            H2[gid * 36 + nt * 4 + tg]       = packh2(h2r[nt][0], h2r[nt][1]);
            H2[(gid + 8) * 36 + nt * 4 + tg] = packh2(h2r[nt][2], h2r[nt][3]);
        }
        __syncwarp();

        long long eA = e_base + m * 16 + gid;
        long long eB = eA + 8;
        float* oA = &g_o[eA * 64];
        float* oB = &g_o[eB * 64];

        // ---- layer 3: K=64 (2 passes of 4 nt) + sequential o store ----
#pragma unroll
        for (int np = 0; np < 2; np++) {
            float d3[4][4];
#pragma unroll
            for (int j = 0; j < 4; j++) {
                int nt = np * 4 + j;
                float bb0 = sb3[nt * 8 + tg * 2], bb1 = sb3[nt * 8 + tg * 2 + 1];
                d3[j][0] = bb0; d3[j][1] = bb1; d3[j][2] = bb0; d3[j][3] = bb1;
            }
#pragma unroll
            for (int kt = 0; kt < 8; kt++) {
                u32 a0 = H2[gid * 36 + 4 * kt + tg];
                u32 a1 = H2[(gid + 8) * 36 + 4 * kt + tg];
#pragma unroll
                for (int j = 0; j < 4; j++) {
                    u32 b = W3u[((np * 4 + j) * 8 + gid) * 36 + 4 * kt + tg];
                    mma_f16(d3[j], a0, a1, b);
                }
            }
#pragma unroll
            for (int j = 0; j < 4; j++) {
                int nt = np * 4 + j;
                int off = nt * 8 + tg * 2;
                st_cs_v2(oA + off, tanh_fast(d3[j][0]) + h2r[nt][0],
                                   tanh_fast(d3[j][1]) + h2r[nt][1]);
                st_cs_v2(oB + off, tanh_fast(d3[j][2]) + h2r[nt][2],
                                   tanh_fast(d3[j][3]) + h2r[nt][3]);
            }
        }
    }
}

// ============ per-node gather-reduce + self-outer (no atomics anywhere) ============
// 4 nodes per 256-thread block; 64 threads per node (thread = dim d).
__global__ void __launch_bounds__(256) reduce_node_kernel(float* __restrict__ out)
{
    int t = threadIdx.x;
    int local = t >> 6;
    int d = t & 63;
    int n = blockIdx.x * 4 + local;

    __shared__ float sA[4][3][8];

    int start = g_start[n];
    int count = g_counts[n];

    float s0 = 0.f, s1 = 0.f, s2 = 0.f;
    for (int q = 0; q < count; q++) {
        int e = g_sorted[start + q];          // broadcast load
        float o = g_o[(long long)e * 64 + d]; // coalesced 256B row
        float4 v = g_v[e];                    // broadcast 16B
        s0 = fmaf(o, v.x, s0);
        s1 = fmaf(o, v.y, s1);
        s2 = fmaf(o, v.z, s2);
    }
    float inv = 1.0f / fmaxf((float)count, 1.0f);
    float c0 = s0 * inv, c1 = s1 * inv, c2 = s2 * inv;

    float* base = &g_summ[(long long)n * 192];
    base[  0 + d] = c0;
    base[ 64 + d] = c1;
    base[128 + d] = c2;

    if (d < 8) {
        sA[local][0][d] = c0;
        sA[local][1][d] = c1;
        sA[local][2][d] = c2;
    }
    __syncthreads();

    float res[8];
#pragma unroll
    for (int a = 0; a < 8; a++)
        res[a] = c0 * sA[local][0][a] + c1 * sA[local][1][a] + c2 * sA[local][2][a];

    float4* op = (float4*)&out[(long long)n * NDD + d * 8];
    op[0] = make_float4(res[0], res[1], res[2], res[3]);
    op[1] = make_float4(res[4], res[5], res[6], res[7]);
}

// ============ edge kernel (recompute from L2-resident aggr) ============
__global__ void __launch_bounds__(256) edge_kernel(
    const int* __restrict__ edge_index,
    float* __restrict__ out)
{
    int t = threadIdx.x;
    int g = t >> 6;
    int d = t & 63;
    int k = blockIdx.x * 4 + g;

    __shared__ float sA[4][2][3][8];

    int i = edge_index[k];
    int j = edge_index[N_EDGES + k];
    const float* Ai = &g_summ[(long long)i * 192];
    const float* Aj = &g_summ[(long long)j * 192];
    float ai0 = Ai[d], ai1 = Ai[64 + d], ai2 = Ai[128 + d];
    float aj0 = Aj[d], aj1 = Aj[64 + d], aj2 = Aj[128 + d];

    if (d < 8) {
        sA[g][0][0][d] = ai0; sA[g][0][1][d] = ai1; sA[g][0][2][d] = ai2;
        sA[g][1][0][d] = aj0; sA[g][1][1][d] = aj1; sA[g][1][2][d] = aj2;
    }
    __syncthreads();

    float res[8];
#pragma unroll
    for (int a = 0; a < 8; a++) {
        res[a] = ai0 * sA[g][0][0][a] + ai1 * sA[g][0][1][a] + ai2 * sA[g][0][2][a]
               + aj0 * sA[g][1][0][a] + aj1 * sA[g][1][1][a] + aj2 * sA[g][1][2][a];
    }

    float* op = &out[(long long)k * NDD + d * 8];
    st_cs_v4(op,     make_float4(res[0], res[1], res[2], res[3]));
    st_cs_v4(op + 4, make_float4(res[4], res[5], res[6], res[7]));
}

extern "C" void kernel_launch(void* const* d_in, const int* in_sizes, int n_in,
                              void* d_out, int out_size)
{
    const float* env_vectors = (const float*)d_in[0];
    const float* atom_attr   = (const float*)d_in[1];
    const int*   env_index   = (const int*)  d_in[2];
    const int*   edge_index  = (const int*)  d_in[3];
    const float* W1 = (const float*)d_in[4];
    const float* b1 = (const float*)d_in[5];
    const float* W2 = (const float*)d_in[6];
    const float* b2 = (const float*)d_in[7];
    const float* W3 = (const float*)d_in[8];
    const float* b3 = (const float*)d_in[9];

    float* out = (float*)d_out;
    float* node_out = out;                       // [50000, 512]
    float* edge_out = out + NODE_OUT_ELEMS;      // [200000, 512]

    size_t smem_bytes = SMEM_WORDS * sizeof(u32);   // 55040
    cudaFuncSetAttribute(env_kernel, cudaFuncAttributeMaxDynamicSharedMemorySize,
                         (int)smem_bytes);

    zero_counts_kernel<<<(N_NODES + 255) / 256, 256>>>();
    hist_kernel<<<(N_ENV + 255) / 256, 256>>>(env_index);
    scan_kernel<<<1, 1024>>>();
    scatter_kernel<<<(N_ENV + 255) / 256, 256>>>(env_index);
    env_kernel<<<(N_WARPS_TOTAL + 7) / 8, 256, smem_bytes>>>(
        env_vectors, atom_attr, env_index, W1, b1, W2, b2, W3, b3);
    reduce_node_kernel<<<N_NODES / 4, 256>>>(node_out);
    edge_kernel<<<N_EDGES / 4, 256>>>(edge_index, edge_out);
}

// round 16
// speedup vs baseline: 1.8730x; 1.2518x over previous
#include <cuda_runtime.h>
#include <cuda_fp16.h>
#include <math.h>

#define N_NODES 50000
#define N_ENV   1000000
#define N_EDGES 200000
#define NDD     512              // D * N_AXIS = 64*8
#define NODE_OUT_ELEMS (N_NODES * NDD)

// Scratch: per-node accumulators. Layout: [node][3][64] (component-major).
// After node_kernel this holds the MEAN (aggr) in place.
__device__ float g_summ[N_NODES * 192];
__device__ float g_cnt[N_NODES];

typedef unsigned long long u64;
typedef unsigned int u32;

__device__ __forceinline__ u64 pack2(float lo, float hi) {
    u64 r; asm("mov.b64 %0, {%1,%2};" : "=l"(r) : "f"(lo), "f"(hi)); return r;
}
__device__ __forceinline__ void unpack2(u64 v, float& lo, float& hi) {
    asm("mov.b64 {%0,%1}, %2;" : "=f"(lo), "=f"(hi) : "l"(v));
}
__device__ __forceinline__ u64 fma2(u64 a, u64 b, u64 c) {
    u64 d; asm("fma.rn.f32x2 %0, %1, %2, %3;" : "=l"(d) : "l"(a), "l"(b), "l"(c)); return d;
}
__device__ __forceinline__ float tanh_fast(float x) {
    float y; asm("tanh.approx.f32 %0, %1;" : "=f"(y) : "f"(x)); return y;
}
__device__ __forceinline__ u32 packh2(float a, float b) {
    __half2 h = __floats2half2_rn(a, b);
    return *reinterpret_cast<u32*>(&h);
}
__device__ __forceinline__ void red_add_v4(float* p, float a, float b, float c, float d) {
    asm volatile("red.global.add.v4.f32 [%0], {%1,%2,%3,%4};"
                 :: "l"(p), "f"(a), "f"(b), "f"(c), "f"(d) : "memory");
}
__device__ __forceinline__ void st_cs_v4(float* p, float4 v) {
    asm volatile("st.global.cs.v4.f32 [%0], {%1,%2,%3,%4};"
                 :: "l"(p), "f"(v.x), "f"(v.y), "f"(v.z), "f"(v.w) : "memory");
}
// mma.m16n8k16 f16 (f32 accum).
// D/C frag: c0=(row=gid,col=2tg) c1=(gid,2tg+1) c2=(gid+8,2tg) c3=(gid+8,2tg+1)
// A frag (16x16 row): a0={A[gid][2tg],A[gid][2tg+1]} a1=rows gid+8 k-lo
//                     a2={A[gid][2tg+8],A[gid][2tg+9]} a3=rows gid+8 k-hi
// B frag (16x8 col):  b0={B[2tg][n=gid],B[2tg+1][gid]} b1={B[2tg+8][gid],B[2tg+9][gid]}
__device__ __forceinline__ void mma_k16(float* d, u32 a0, u32 a1, u32 a2, u32 a3,
                                        u32 b0, u32 b1) {
    asm volatile(
        "mma.sync.aligned.m16n8k16.row.col.f32.f16.f16.f32 "
        "{%0,%1,%2,%3},{%4,%5,%6,%7},{%8,%9},{%0,%1,%2,%3};"
        : "+f"(d[0]), "+f"(d[1]), "+f"(d[2]), "+f"(d[3])
        : "r"(a0), "r"(a1), "r"(a2), "r"(a3), "r"(b0), "r"(b1));
}

__global__ void zero_kernel() {
    int i = blockIdx.x * blockDim.x + threadIdx.x;
    int stride = gridDim.x * blockDim.x;
    float4* p = (float4*)g_summ;
    const float4 z = make_float4(0.f, 0.f, 0.f, 0.f);
    for (int k = i; k < N_NODES * 48; k += stride) p[k] = z;
    for (int k = i; k < N_NODES; k += stride) g_cnt[k] = 0.f;
}

// Shared memory word map (u32 units):
#define OFF_W1  0        // 288 f32
#define OFF_B1  288      // 32 f32
#define OFF_B2  320      // 64 f32
#define OFF_B3  384      // 64 f32
#define OFF_W2H 448      // 64 n x 20 words (f16x2 pairs along k; 16 used)
#define OFF_W3H 1728     // 64 n x 36 words (32 used)
#define OFF_H   4032     // per warp: H1 32 rows x 20 words (layer-1 activations only)
#define WARP_H_WORDS (32 * 20)             // 640
#define SMEM_WORDS (OFF_H + 8 * WARP_H_WORDS)  // 9152 words = 36608 B
#define N_WARPS_TOTAL (N_ENV / 32)         // 31250

__global__ void __launch_bounds__(256, 3) env_kernel(
    const float* __restrict__ env_vectors,
    const float* __restrict__ atom_attr,
    const int*   __restrict__ env_index,
    const float* __restrict__ W1, const float* __restrict__ b1,
    const float* __restrict__ W2, const float* __restrict__ b2,
    const float* __restrict__ W3, const float* __restrict__ b3)
{
    extern __shared__ __align__(16) u32 smu[];
    float* smf = (float*)smu;
    int tid = threadIdx.x;

    // ---- stage weights ----
    for (int i = tid; i < 288; i += 256) smf[OFF_W1 + i] = W1[i];
    for (int i = tid; i < 32;  i += 256) smf[OFF_B1 + i] = b1[i];
    for (int i = tid; i < 64;  i += 256) smf[OFF_B2 + i] = b2[i];
    for (int i = tid; i < 64;  i += 256) smf[OFF_B3 + i] = b3[i];
    // W2 [32k x 64n] -> f16x2 pairs along k: word(n, kw) kw<16, stride 20
    for (int i = tid; i < 64 * 16; i += 256) {
        int n = i >> 4, kw = i & 15;
        smu[OFF_W2H + n * 20 + kw] = packh2(W2[(2 * kw) * 64 + n], W2[(2 * kw + 1) * 64 + n]);
    }
    // W3 [64k x 64n]: kw<32, stride 36
    for (int i = tid; i < 64 * 32; i += 256) {
        int n = i >> 5, kw = i & 31;
        smu[OFF_W3H + n * 36 + kw] = packh2(W3[(2 * kw) * 64 + n], W3[(2 * kw + 1) * 64 + n]);
    }
    __syncthreads();

    int wid  = tid >> 5;
    int lane = tid & 31;
    int warpg = blockIdx.x * 8 + wid;
    if (warpg >= N_WARPS_TOTAL) return;
    int e_base = warpg * 32;

    u32* H1 = &smu[OFF_H + wid * WARP_H_WORDS];          // 32 rows x 20 words
    const float* sW1 = &smf[OFF_W1];
    const float* sb1 = &smf[OFF_B1];
    const float* sb2 = &smf[OFF_B2];
    const float* sb3 = &smf[OFF_B3];

    // ================= scalar layer 1 (exact fp32), lane = env =================
    {
        int e = e_base + lane;
        float vx = env_vectors[3 * e + 0];
        float vy = env_vectors[3 * e + 1];
        float vz = env_vectors[3 * e + 2];
        float r = sqrtf(vx * vx + vy * vy + vz * vz);
        float inv_r = 1.0f / r;
        float snorm;
        if (r < 3.0f) snorm = inv_r;
        else if (r < 6.0f) {
            float u = (r - 6.0f) * (-1.0f / 3.0f);
            snorm = inv_r * (u * u * u * (10.0f + u * (-15.0f + 6.0f * u)) + 1.0f);
        } else snorm = 0.0f;

        int i0 = env_index[e];
        int i1 = env_index[N_ENV + e];
        float4 a0 = *(const float4*)&atom_attr[4 * i0];
        float4 a1 = *(const float4*)&atom_attr[4 * i1];

        u64 inp[9];
        inp[0] = pack2(snorm, snorm);
        inp[1] = pack2(a0.x, a0.x); inp[2] = pack2(a0.y, a0.y);
        inp[3] = pack2(a0.z, a0.z); inp[4] = pack2(a0.w, a0.w);
        inp[5] = pack2(a1.x, a1.x); inp[6] = pack2(a1.y, a1.y);
        inp[7] = pack2(a1.z, a1.z); inp[8] = pack2(a1.w, a1.w);

        float h1[32];
#pragma unroll
        for (int j = 0; j < 32; j += 4) {
            ulonglong2 b = *(const ulonglong2*)&sb1[j];
            u64 s0 = b.x, s1 = b.y;
#pragma unroll
            for (int i = 0; i < 9; i++) {
                ulonglong2 w = *(const ulonglong2*)&sW1[i * 32 + j];
                s0 = fma2(inp[i], w.x, s0);
                s1 = fma2(inp[i], w.y, s1);
            }
            float x0, x1, x2, x3;
            unpack2(s0, x0, x1); unpack2(s1, x2, x3);
            h1[j + 0] = tanh_fast(x0);
            h1[j + 1] = tanh_fast(x1);
            h1[j + 2] = tanh_fast(x2);
            h1[j + 3] = tanh_fast(x3);
        }
        // stage h1 as f16x2 pairs: row=lane, 16 words, stride 20
#pragma unroll
        for (int k = 0; k < 16; k++)
            H1[lane * 20 + k] = packh2(h1[2 * k], h1[2 * k + 1]);
    }
    __syncwarp();

    int gid = lane >> 2;       // 0..7
    int tg  = lane & 3;        // 0..3
    const u32* W2u = &smu[OFF_W2H];
    const u32* W3u = &smu[OFF_W3H];

    for (int m = 0; m < 2; m++) {
        int r1A = (m * 16 + gid) * 20;
        int r1B = (m * 16 + gid + 8) * 20;

        // ---- layer 2: K=32 (2 k16 steps), all 8 nt ----
        float h2r[8][4];
#pragma unroll
        for (int nt = 0; nt < 8; nt++) {
            float bb0 = sb2[nt * 8 + tg * 2], bb1 = sb2[nt * 8 + tg * 2 + 1];
            h2r[nt][0] = bb0; h2r[nt][1] = bb1; h2r[nt][2] = bb0; h2r[nt][3] = bb1;
        }
#pragma unroll
        for (int kk = 0; kk < 2; kk++) {
            u32 a0 = H1[r1A + 8 * kk + tg];
            u32 a1 = H1[r1B + 8 * kk + tg];
            u32 a2 = H1[r1A + 8 * kk + tg + 4];
            u32 a3 = H1[r1B + 8 * kk + tg + 4];
#pragma unroll
            for (int nt = 0; nt < 8; nt++) {
                u32 b0 = W2u[(nt * 8 + gid) * 20 + 8 * kk + tg];
                u32 b1 = W2u[(nt * 8 + gid) * 20 + 8 * kk + tg + 4];
                mma_k16(h2r[nt], a0, a1, a2, a3, b0, b1);
            }
        }
#pragma unroll
        for (int nt = 0; nt < 8; nt++) {
            h2r[nt][0] = tanh_fast(h2r[nt][0]);
            h2r[nt][1] = tanh_fast(h2r[nt][1]);
            h2r[nt][2] = tanh_fast(h2r[nt][2]);
            h2r[nt][3] = tanh_fast(h2r[nt][3]);
        }

        // ---- pack layer-3 A-fragments straight from registers (C-frag == A-frag) ----
        // k16 block kk covers h2 cols 16kk..16kk+15 = nt 2kk (lo) and 2kk+1 (hi)
        u32 aP[4][4];
#pragma unroll
        for (int kk = 0; kk < 4; kk++) {
            aP[kk][0] = packh2(h2r[2 * kk][0],     h2r[2 * kk][1]);      // rows gid,   k-lo
            aP[kk][1] = packh2(h2r[2 * kk][2],     h2r[2 * kk][3]);      // rows gid+8, k-lo
            aP[kk][2] = packh2(h2r[2 * kk + 1][0], h2r[2 * kk + 1][1]);  // rows gid,   k-hi
            aP[kk][3] = packh2(h2r[2 * kk + 1][2], h2r[2 * kk + 1][3]);  // rows gid+8, k-hi
        }

        // per-m epilogue context
        int eA = e_base + m * 16 + gid;
        int eB = eA + 8;
        int odd = tg & 1;
        int e_use = odd ? eB : eA;
        float vx = env_vectors[3 * e_use + 0];
        float vy = env_vectors[3 * e_use + 1];
        float vz = env_vectors[3 * e_use + 2];
        int n_use = env_index[N_ENV + e_use];
        float* base = &g_summ[(long long)n_use * 192];
        int col4 = (tg & 2) * 2;

        // ---- layer 3: K=64 (4 k16 steps), 2 passes of 4 nt, A from regs ----
#pragma unroll
        for (int np = 0; np < 2; np++) {
            float d3[4][4];
#pragma unroll
            for (int j = 0; j < 4; j++) {
                int nt = np * 4 + j;
                float bb0 = sb3[nt * 8 + tg * 2], bb1 = sb3[nt * 8 + tg * 2 + 1];
                d3[j][0] = bb0; d3[j][1] = bb1; d3[j][2] = bb0; d3[j][3] = bb1;
            }
#pragma unroll
            for (int kk = 0; kk < 4; kk++) {
#pragma unroll
                for (int j = 0; j < 4; j++) {
                    int nrow = (np * 4 + j) * 8 + gid;
                    u32 b0 = W3u[nrow * 36 + 8 * kk + tg];
                    u32 b1 = W3u[nrow * 36 + 8 * kk + tg + 4];
                    mma_k16(d3[j], aP[kk][0], aP[kk][1], aP[kk][2], aP[kk][3], b0, b1);
                }
            }
            // tanh + residual, pair-shuffle to 4-wide, red.v4 scatter
#pragma unroll
            for (int j = 0; j < 4; j++) {
                int nt = np * 4 + j;
                float oA0 = tanh_fast(d3[j][0]) + h2r[nt][0];
                float oA1 = tanh_fast(d3[j][1]) + h2r[nt][1];
                float oB0 = tanh_fast(d3[j][2]) + h2r[nt][2];
                float oB1 = tanh_fast(d3[j][3]) + h2r[nt][3];
                float pA0 = __shfl_xor_sync(0xffffffff, oA0, 1);
                float pA1 = __shfl_xor_sync(0xffffffff, oA1, 1);
                float pB0 = __shfl_xor_sync(0xffffffff, oB0, 1);
                float pB1 = __shfl_xor_sync(0xffffffff, oB1, 1);
                float q0 = odd ? pB0 : oA0;
                float q1 = odd ? pB1 : oA1;
                float q2 = odd ? oB0 : pA0;
                float q3 = odd ? oB1 : pA1;
                int off = nt * 8 + col4;
                red_add_v4(base +   0 + off, q0 * vx, q1 * vx, q2 * vx, q3 * vx);
                red_add_v4(base +  64 + off, q0 * vy, q1 * vy, q2 * vy, q3 * vy);
                red_add_v4(base + 128 + off, q0 * vz, q1 * vz, q2 * vz, q3 * vz);
            }
        }
        if (tg == 0) {
            atomicAdd(&g_cnt[env_index[N_ENV + eA]], 1.0f);
            atomicAdd(&g_cnt[env_index[N_ENV + eB]], 1.0f);
        }
    }
}

// 4 nodes per 256-thread block. Computes aggr (mean), writes node_desc, AND
// writes aggr back into g_summ in place for the edge kernel to reuse.
__global__ void __launch_bounds__(256) node_kernel(float* __restrict__ out)
{
    int t = threadIdx.x;
    int local = t >> 6;
    int d = t & 63;
    int n = blockIdx.x * 4 + local;

    __shared__ float sA[4][3][8];

    float cnt = g_cnt[n];
    float inv = 1.0f / fmaxf(cnt, 1.0f);
    float* base = &g_summ[(long long)n * 192];
    float c0 = base[  0 + d] * inv;
    float c1 = base[ 64 + d] * inv;
    float c2 = base[128 + d] * inv;

    if (d < 8) {
        sA[local][0][d] = c0;
        sA[local][1][d] = c1;
        sA[local][2][d] = c2;
    }
    base[  0 + d] = c0;
    base[ 64 + d] = c1;
    base[128 + d] = c2;
    __syncthreads();

    float res[8];
#pragma unroll
    for (int a = 0; a < 8; a++)
        res[a] = c0 * sA[local][0][a] + c1 * sA[local][1][a] + c2 * sA[local][2][a];

    float4* op = (float4*)&out[(long long)n * NDD + d * 8];
    op[0] = make_float4(res[0], res[1], res[2], res[3]);
    op[1] = make_float4(res[4], res[5], res[6], res[7]);
}

// 4 edges per 256-thread block; recompute both endpoint descriptors from the
// small (38MB, L2-resident) aggr buffer.
__global__ void __launch_bounds__(256) edge_kernel(
    const int* __restrict__ edge_index,
    float* __restrict__ out)
{
    int t = threadIdx.x;
    int g = t >> 6;
    int d = t & 63;
    int k = blockIdx.x * 4 + g;

    __shared__ float sA[4][2][3][8];

    int i = edge_index[k];
    int j = edge_index[N_EDGES + k];
    const float* Ai = &g_summ[(long long)i * 192];
    const float* Aj = &g_summ[(long long)j * 192];
    float ai0 = Ai[d], ai1 = Ai[64 + d], ai2 = Ai[128 + d];
    float aj0 = Aj[d], aj1 = Aj[64 + d], aj2 = Aj[128 + d];

    if (d < 8) {
        sA[g][0][0][d] = ai0; sA[g][0][1][d] = ai1; sA[g][0][2][d] = ai2;
        sA[g][1][0][d] = aj0; sA[g][1][1][d] = aj1; sA[g][1][2][d] = aj2;
    }
    __syncthreads();

    float res[8];
#pragma unroll
    for (int a = 0; a < 8; a++) {
        res[a] = ai0 * sA[g][0][0][a] + ai1 * sA[g][0][1][a] + ai2 * sA[g][0][2][a]
               + aj0 * sA[g][1][0][a] + aj1 * sA[g][1][1][a] + aj2 * sA[g][1][2][a];
    }

    float* op = &out[(long long)k * NDD + d * 8];
    st_cs_v4(op,     make_float4(res[0], res[1], res[2], res[3]));
    st_cs_v4(op + 4, make_float4(res[4], res[5], res[6], res[7]));
}

extern "C" void kernel_launch(void* const* d_in, const int* in_sizes, int n_in,
                              void* d_out, int out_size)
{
    const float* env_vectors = (const float*)d_in[0];
    const float* atom_attr   = (const float*)d_in[1];
    const int*   env_index   = (const int*)  d_in[2];
    const int*   edge_index  = (const int*)  d_in[3];
    const float* W1 = (const float*)d_in[4];
    const float* b1 = (const float*)d_in[5];
    const float* W2 = (const float*)d_in[6];
    const float* b2 = (const float*)d_in[7];
    const float* W3 = (const float*)d_in[8];
    const float* b3 = (const float*)d_in[9];

    float* out = (float*)d_out;
    float* node_out = out;                       // [50000, 512]
    float* edge_out = out + NODE_OUT_ELEMS;      // [200000, 512]

    size_t smem_bytes = SMEM_WORDS * sizeof(u32);   // 36608
    cudaFuncSetAttribute(env_kernel, cudaFuncAttributeMaxDynamicSharedMemorySize,
                         (int)smem_bytes);

    zero_kernel<<<2048, 256>>>();
    env_kernel<<<(N_WARPS_TOTAL + 7) / 8, 256, smem_bytes>>>(
        env_vectors, atom_attr, env_index, W1, b1, W2, b2, W3, b3);
    node_kernel<<<N_NODES / 4, 256>>>(node_out);
    edge_kernel<<<N_EDGES / 4, 256>>>(edge_index, edge_out);
}